// round 4
// baseline (speedup 1.0000x reference)
#include <cuda_runtime.h>
#include <cuda_bf16.h>
#include <mma.h>
#include <math.h>

using namespace nvcuda;

// Problem constants (fixed shapes)
#define BSZ   4
#define SEQ   1024
#define DM    512
#define NH    8
#define DQ    64
#define M_TOT (BSZ*SEQ)     // 4096 tokens
#define N_TOT (2*DM)        // 1024: [Q feats | K feats]
#define NBH   (BSZ*NH)      // 32 (batch,head) pairs

// -------------------- device scratch --------------------
__device__ float         g_QK[M_TOT * N_TOT];     // 16 MB fp32 GEMM output
__device__ __nv_bfloat16 g_Abf[M_TOT * DM];       // 4 MB  bf16 ctx
__device__ __nv_bfloat16 g_Bbf[N_TOT * DM];       // 1 MB  bf16 [Wq;Wk]
__device__ float g_Sf[NBH * SEQ];
__device__ float g_Sb[NBH * SEQ];
__device__ float g_G [NBH * SEQ];                 // exclusive prefix sums of g
__device__ float g_band[NBH * SEQ];               // ph_i
__device__ float g_E [NBH * SEQ];                 // exp(g_i) = ph_i + 1e-9

// -------------------- Kernel 0: fp32 -> bf16 conversion prepass ----------------
// groups of 8 floats -> 8 bf16 (one uint4 store)
__global__ __launch_bounds__(256) void cvt_kernel(
    const float* __restrict__ ctx,
    const float* __restrict__ Wq,
    const float* __restrict__ Wk)
{
    const int CTX_G = (M_TOT * DM) / 8;     // 262144
    const int W_G   = (DM * DM) / 8;        // 32768 per weight matrix
    int idx = blockIdx.x * 256 + threadIdx.x;
    if (idx >= CTX_G + 2 * W_G) return;

    const float* src;
    __nv_bfloat16* dst;
    if (idx < CTX_G) {
        src = ctx + (size_t)idx * 8;
        dst = g_Abf + (size_t)idx * 8;
    } else if (idx < CTX_G + W_G) {
        int j = idx - CTX_G;
        src = Wq + (size_t)j * 8;
        dst = g_Bbf + (size_t)j * 8;
    } else {
        int j = idx - CTX_G - W_G;
        src = Wk + (size_t)j * 8;
        dst = g_Bbf + (size_t)(W_G * 8) + (size_t)j * 8;
    }
    float4 v0 = *(const float4*)(src);
    float4 v1 = *(const float4*)(src + 4);
    __nv_bfloat162 b0 = __floats2bfloat162_rn(v0.x, v0.y);
    __nv_bfloat162 b1 = __floats2bfloat162_rn(v0.z, v0.w);
    __nv_bfloat162 b2 = __floats2bfloat162_rn(v1.x, v1.y);
    __nv_bfloat162 b3 = __floats2bfloat162_rn(v1.z, v1.w);
    uint4 packed;
    packed.x = *(unsigned*)&b0; packed.y = *(unsigned*)&b1;
    packed.z = *(unsigned*)&b2; packed.w = *(unsigned*)&b3;
    *(uint4*)dst = packed;
}

// -------------------- Kernel 1: double-buffered bf16 WMMA GEMM -----------------
// C[m,n] = sum_k A[m,k] * B[n,k],  A=(4096,512) bf16, B=(1024,512) bf16
#define BM  128
#define BN  128
#define BKK 32
#define KPAD 40   // 80 bytes/row: multiple of 16 -> uint4 STS aligned

__global__ __launch_bounds__(256) void gemm_kernel()
{
    __shared__ __nv_bfloat16 As[2][BM][KPAD];
    __shared__ __nv_bfloat16 Bs[2][BN][KPAD];

    const int bn = blockIdx.x;           // 0..7
    const int bm = blockIdx.y;           // 0..31
    const int tid = threadIdx.x;
    const int warp = tid >> 5;
    const int wm = warp & 3;
    const int wn = warp >> 2;

    // load mapping: 512 uint4-groups per tile, 2 per thread
    const int g0 = tid, g1 = tid + 256;
    const int r0 = g0 >> 2, c0 = (g0 & 3) * 8;
    const int r1 = g1 >> 2, c1 = (g1 & 3) * 8;

    const __nv_bfloat16* Ag = g_Abf + (size_t)(bm * BM) * DM;
    const __nv_bfloat16* Bg = g_Bbf + (size_t)(bn * BN) * DM;

    wmma::fragment<wmma::accumulator,16,16,16,float> acc[2][4];
    #pragma unroll
    for (int m = 0; m < 2; m++)
        #pragma unroll
        for (int n = 0; n < 4; n++)
            wmma::fill_fragment(acc[m][n], 0.0f);

    // preload tile 0
    {
        uint4 a0 = *(const uint4*)(Ag + (size_t)r0 * DM + c0);
        uint4 a1 = *(const uint4*)(Ag + (size_t)r1 * DM + c1);
        uint4 b0 = *(const uint4*)(Bg + (size_t)r0 * DM + c0);
        uint4 b1 = *(const uint4*)(Bg + (size_t)r1 * DM + c1);
        *(uint4*)&As[0][r0][c0] = a0;  *(uint4*)&As[0][r1][c1] = a1;
        *(uint4*)&Bs[0][r0][c0] = b0;  *(uint4*)&Bs[0][r1][c1] = b1;
    }
    __syncthreads();

    const int NIT = DM / BKK;  // 16
    for (int kt = 0; kt < NIT; kt++) {
        int cur = kt & 1;
        uint4 a0, a1, b0, b1;
        if (kt + 1 < NIT) {
            int kg = (kt + 1) * BKK;
            a0 = *(const uint4*)(Ag + (size_t)r0 * DM + kg + c0);
            a1 = *(const uint4*)(Ag + (size_t)r1 * DM + kg + c1);
            b0 = *(const uint4*)(Bg + (size_t)r0 * DM + kg + c0);
            b1 = *(const uint4*)(Bg + (size_t)r1 * DM + kg + c1);
        }

        #pragma unroll
        for (int kk = 0; kk < BKK; kk += 16) {
            wmma::fragment<wmma::matrix_a,16,16,16,__nv_bfloat16,wmma::row_major> af[2];
            wmma::fragment<wmma::matrix_b,16,16,16,__nv_bfloat16,wmma::col_major> bf[4];
            #pragma unroll
            for (int m = 0; m < 2; m++)
                wmma::load_matrix_sync(af[m], &As[cur][wm*32 + m*16][kk], KPAD);
            #pragma unroll
            for (int n = 0; n < 4; n++)
                wmma::load_matrix_sync(bf[n], &Bs[cur][wn*64 + n*16][kk], KPAD);
            #pragma unroll
            for (int m = 0; m < 2; m++)
                #pragma unroll
                for (int n = 0; n < 4; n++)
                    wmma::mma_sync(acc[m][n], af[m], bf[n], acc[m][n]);
        }

        if (kt + 1 < NIT) {
            int nxt = cur ^ 1;
            *(uint4*)&As[nxt][r0][c0] = a0;  *(uint4*)&As[nxt][r1][c1] = a1;
            *(uint4*)&Bs[nxt][r0][c0] = b0;  *(uint4*)&Bs[nxt][r1][c1] = b1;
        }
        __syncthreads();
    }

    #pragma unroll
    for (int m = 0; m < 2; m++)
        #pragma unroll
        for (int n = 0; n < 4; n++)
            wmma::store_matrix_sync(
                &g_QK[(size_t)(bm*BM + wm*32 + m*16)*N_TOT + bn*BN + wn*64 + n*16],
                acc[m][n], N_TOT, wmma::mem_row_major);
}

// -------------------- Kernel 2: banded dot products (bias folded) --------------
__global__ __launch_bounds__(256) void band_kernel(
    const float* __restrict__ bq, const float* __restrict__ bk)
{
    int row  = blockIdx.x;               // b*SEQ + i
    int b    = row >> 10;
    int i    = row & (SEQ - 1);
    int h    = threadIdx.x >> 5;
    int lane = threadIdx.x & 31;
    int c    = h*DQ + lane*2;

    float2 qv  = *(const float2*)&g_QK[(size_t)row*N_TOT + c];
    float2 bqv = *(const float2*)&bq[c];
    float2 bkv = *(const float2*)&bk[c];
    float q0 = qv.x + bqv.x, q1 = qv.y + bqv.y;

    float sf = 0.f, sb = 0.f;
    if (i < SEQ-1) {
        float2 kv = *(const float2*)&g_QK[(size_t)(row+1)*N_TOT + DM + c];
        sf = q0*(kv.x + bkv.x) + q1*(kv.y + bkv.y);
    }
    if (i > 0) {
        float2 kv = *(const float2*)&g_QK[(size_t)(row-1)*N_TOT + DM + c];
        sb = q0*(kv.x + bkv.x) + q1*(kv.y + bkv.y);
    }
    #pragma unroll
    for (int off = 16; off; off >>= 1) {
        sf += __shfl_down_sync(0xffffffffu, sf, off);
        sb += __shfl_down_sync(0xffffffffu, sb, off);
    }
    if (lane == 0) {
        int idx = (b*NH + h)*SEQ + i;
        g_Sf[idx] = sf * (1.0f / DM);
        g_Sb[idx] = sb * (1.0f / DM);
    }
}

// -------------------- Kernel 3: softmax -> g -> block prefix scan --------------
__global__ __launch_bounds__(1024) void scan_kernel(const int* __restrict__ amask)
{
    int bh = blockIdx.x;
    int b  = bh >> 3;
    int t  = threadIdx.x;

    __shared__ float b_sh[SEQ];
    __shared__ float wsum[32];

    float sf = g_Sf[bh*SEQ + t];
    float sb = g_Sb[bh*SEQ + t];
    bool vf = (t < SEQ-1) && (amask[b*SEQ + t + 1] != 0);
    bool vb = (t > 0)     && (amask[b*SEQ + t - 1] != 0);

    float a, bb;
    if (vf | vb) {
        float m  = fmaxf(vf ? sf : -3.4e38f, vb ? sb : -3.4e38f);
        float ea = vf ? __expf(sf - m) : 0.f;
        float eb = vb ? __expf(sb - m) : 0.f;
        float den = ea + eb;
        a  = ea / den;
        bb = eb / den;
    } else {
        a = bb = 1.0f / SEQ;
    }
    b_sh[t] = bb;
    __syncthreads();

    float g = 0.f;
    if (t < SEQ-1) {
        float ph = sqrtf(a * b_sh[t+1] + 1e-9f);
        g_band[bh*SEQ + t] = ph;
        g_E[bh*SEQ + t]    = ph + 1e-9f;      // = exp(g) exactly
        g = logf(ph + 1e-9f);
    } else {
        g_band[bh*SEQ + t] = 0.f;
        g_E[bh*SEQ + t]    = 1.0f;
    }

    int lane = t & 31, wid = t >> 5;
    float incl = g;
    #pragma unroll
    for (int off = 1; off < 32; off <<= 1) {
        float n = __shfl_up_sync(0xffffffffu, incl, off);
        if (lane >= off) incl += n;
    }
    if (lane == 31) wsum[wid] = incl;
    __syncthreads();
    if (wid == 0) {
        float w = wsum[lane];
        #pragma unroll
        for (int off = 1; off < 32; off <<= 1) {
            float n = __shfl_up_sync(0xffffffffu, w, off);
            if (lane >= off) w += n;
        }
        wsum[lane] = w;
    }
    __syncthreads();
    float base = (wid > 0) ? wsum[wid-1] : 0.f;
    g_G[bh*SEQ + t] = base + incl - g;   // exclusive prefix
}

// -------------------- Kernel 4: materialize outputs ---------------------------
// Each thread: 16 consecutive k of one row; 1 exp + 15 chained FMULs.
__global__ __launch_bounds__(256) void out_kernel(float* __restrict__ out, int write_ph)
{
    const float EPS = 1e-9f;
    const float SQRT_EPS = 3.1622776601683795e-5f;

    int t   = threadIdx.x;
    int row = blockIdx.x * 4 + (t >> 6);      // bh*SEQ + i
    int bh  = row >> 10;
    int i   = row & (SEQ - 1);
    int k0  = (t & 63) << 4;                  // chunk of 16

    const float* Gp = g_G + bh*SEQ;
    const float* Ep = g_E + bh*SEQ;
    float Gi = Gp[i];

    float v[16];

    if (k0 > i) {
        // all k > i: v[k] = exp(G[k]-G[i]); ascending chain
        float4 e0 = *(const float4*)(Ep + k0);
        float4 e1 = *(const float4*)(Ep + k0 + 4);
        float4 e2 = *(const float4*)(Ep + k0 + 8);
        float4 e3 = *(const float4*)(Ep + k0 + 12);
        float ev[16] = {e0.x,e0.y,e0.z,e0.w, e1.x,e1.y,e1.z,e1.w,
                        e2.x,e2.y,e2.z,e2.w, e3.x,e3.y,e3.z,e3.w};
        v[0] = __expf(Gp[k0] - Gi);
        #pragma unroll
        for (int j = 1; j < 16; j++) v[j] = v[j-1] * ev[j-1];
        #pragma unroll
        for (int j = 0; j < 16; j++) v[j] += EPS;
    } else if (k0 + 15 < i) {
        // all k < i: v[k] = exp(G[i]-G[k]); descending chain
        float4 e0 = *(const float4*)(Ep + k0);
        float4 e1 = *(const float4*)(Ep + k0 + 4);
        float4 e2 = *(const float4*)(Ep + k0 + 8);
        float4 e3 = *(const float4*)(Ep + k0 + 12);
        float ev[16] = {e0.x,e0.y,e0.z,e0.w, e1.x,e1.y,e1.z,e1.w,
                        e2.x,e2.y,e2.z,e2.w, e3.x,e3.y,e3.z,e3.w};
        v[15] = __expf(Gi - Gp[k0 + 15]);
        #pragma unroll
        for (int j = 14; j >= 0; j--) v[j] = v[j+1] * ev[j];
        #pragma unroll
        for (int j = 0; j < 16; j++) v[j] += EPS;
    } else {
        // chunk straddles the diagonal: per-element
        float4 g0 = *(const float4*)(Gp + k0);
        float4 g1 = *(const float4*)(Gp + k0 + 4);
        float4 g2 = *(const float4*)(Gp + k0 + 8);
        float4 g3 = *(const float4*)(Gp + k0 + 12);
        float gv[16] = {g0.x,g0.y,g0.z,g0.w, g1.x,g1.y,g1.z,g1.w,
                        g2.x,g2.y,g2.z,g2.w, g3.x,g3.y,g3.z,g3.w};
        #pragma unroll
        for (int j = 0; j < 16; j++) {
            int k = k0 + j;
            v[j] = (k == i) ? SQRT_EPS
                            : (__expf((k > i) ? gv[j] - Gi : Gi - gv[j]) + EPS);
        }
    }

    size_t off = (size_t)row * SEQ + k0;
    __stcs((float4*)(out + off),      make_float4(v[0],  v[1],  v[2],  v[3]));
    __stcs((float4*)(out + off + 4),  make_float4(v[4],  v[5],  v[6],  v[7]));
    __stcs((float4*)(out + off + 8),  make_float4(v[8],  v[9],  v[10], v[11]));
    __stcs((float4*)(out + off + 12), make_float4(v[12], v[13], v[14], v[15]));

    if (write_ph) {
        float p[16];
        #pragma unroll
        for (int j = 0; j < 16; j++) p[j] = SQRT_EPS;
        int d = (i - 1) - k0;
        if (d >= 0 && d < 16) p[d] = g_band[bh*SEQ + i - 1];
        d = (i + 1) - k0;
        if (d >= 0 && d < 16) p[d] = g_band[bh*SEQ + i];
        size_t poff = (size_t)NBH*SEQ*SEQ + off;
        __stcs((float4*)(out + poff),      make_float4(p[0],  p[1],  p[2],  p[3]));
        __stcs((float4*)(out + poff + 4),  make_float4(p[4],  p[5],  p[6],  p[7]));
        __stcs((float4*)(out + poff + 8),  make_float4(p[8],  p[9],  p[10], p[11]));
        __stcs((float4*)(out + poff + 12), make_float4(p[12], p[13], p[14], p[15]));
    }
}

// -------------------- launch ---------------------------------------------------
extern "C" void kernel_launch(void* const* d_in, const int* in_sizes, int n_in,
                              void* d_out, int out_size)
{
    const float* ctx   = (const float*)d_in[0];
    const int*   amask = (const int*)  d_in[1];
    const float* Wq    = (const float*)d_in[2];
    const float* bq    = (const float*)d_in[3];
    const float* Wk    = (const float*)d_in[4];
    const float* bk    = (const float*)d_in[5];
    float* out = (float*)d_out;

    long long total = (long long)NBH * SEQ * SEQ;
    int write_ph = ((long long)out_size >= 2 * total) ? 1 : 0;

    const int CVT_G = (M_TOT*DM + 2*DM*DM) / 8;   // 327680 groups
    cvt_kernel<<<(CVT_G + 255) / 256, 256>>>(ctx, Wq, Wk);

    dim3 ggrid(N_TOT / BN, M_TOT / BM);           // (8, 32)
    gemm_kernel<<<ggrid, 256>>>();
    band_kernel<<<M_TOT, 256>>>(bq, bk);
    scan_kernel<<<NBH, 1024>>>(amask);
    out_kernel<<<NBH * SEQ / 4, 256>>>(out, write_ph);
}